// round 1
// baseline (speedup 1.0000x reference)
#include <cuda_runtime.h>
#include <cuda_bf16.h>
#include <math_constants.h>

// Problem constants
#define BATCH 4
#define SEQ 2048
#define DIM 960
#define NH 15
#define NKV 5
#define HD 64
#define GQA 3           // NH / NKV
#define MTOK (BATCH*SEQ) // 8192 tokens

// ---------------- scratch (device globals; no allocations) ----------------
__device__ float g_q[(size_t)MTOK * NH * HD];     // 8192 x 960
__device__ float g_k[(size_t)MTOK * NKV * HD];    // 8192 x 320
__device__ float g_v[(size_t)MTOK * NKV * HD];    // 8192 x 320
__device__ float g_attn[(size_t)MTOK * NH * HD];  // 8192 x 960

// ---------------- GEMM: C[M,N] = A[M,K] @ B[K,N], row-major fp32 ----------
// 64x64 block tile, 16 k-step, 256 threads, 4x4 register tile per thread.
#define TM 64
#define TN 64
#define TK 16

__global__ void __launch_bounds__(256)
gemm_f32_kernel(const float* __restrict__ A, const float* __restrict__ B,
                float* __restrict__ C, int M, int N, int K) {
    __shared__ float As[TM][TK];     // [m][k]
    __shared__ float Bs[TK][TN];     // [k][n]

    const int tid = threadIdx.x;
    const int tx = tid & 15;         // n-group
    const int ty = tid >> 4;         // m-group
    const int m0 = blockIdx.y * TM;
    const int n0 = blockIdx.x * TN;

    float acc[4][4];
#pragma unroll
    for (int i = 0; i < 4; i++)
#pragma unroll
        for (int j = 0; j < 4; j++) acc[i][j] = 0.f;

    for (int k0 = 0; k0 < K; k0 += TK) {
        // Load A tile (64x16 = 1024 elems, 4 per thread), coalesced over k
#pragma unroll
        for (int i = 0; i < 4; i++) {
            int idx = tid + i * 256;
            int m = idx >> 4, k = idx & 15;
            As[m][k] = A[(size_t)(m0 + m) * K + k0 + k];
        }
        // Load B tile (16x64), coalesced over n
#pragma unroll
        for (int i = 0; i < 4; i++) {
            int idx = tid + i * 256;
            int k = idx >> 6, n = idx & 63;
            Bs[k][n] = B[(size_t)(k0 + k) * N + n0 + n];
        }
        __syncthreads();

#pragma unroll
        for (int kk = 0; kk < TK; kk++) {
            float a[4];
#pragma unroll
            for (int i = 0; i < 4; i++) a[i] = As[ty * 4 + i][kk];
            float4 b4 = *(const float4*)&Bs[kk][tx * 4];
            float bb[4] = {b4.x, b4.y, b4.z, b4.w};
#pragma unroll
            for (int i = 0; i < 4; i++)
#pragma unroll
                for (int j = 0; j < 4; j++)
                    acc[i][j] = fmaf(a[i], bb[j], acc[i][j]);
        }
        __syncthreads();
    }

#pragma unroll
    for (int i = 0; i < 4; i++) {
        int m = m0 + ty * 4 + i;
        float4 r = make_float4(acc[i][0], acc[i][1], acc[i][2], acc[i][3]);
        *(float4*)&C[(size_t)m * N + n0 + tx * 4] = r;
    }
}

// ---------------- RoPE (interleaved pairs), in-place -----------------------
__global__ void rope_kernel(float* __restrict__ buf,
                            const float* __restrict__ cosb,
                            const float* __restrict__ sinb,
                            int nheads, int total) {
    int idx = blockIdx.x * blockDim.x + threadIdx.x;
    if (idx >= total) return;
    int i = idx & 31;                 // pair index within head (HD/2 = 32)
    int rest = idx >> 5;
    int h = rest % nheads;
    int tg = rest / nheads;           // global token 0..8191
    int t = tg & (SEQ - 1);           // position within sequence
    float c = cosb[t * 32 + i];
    float s = sinb[t * 32 + i];
    float* p = buf + ((size_t)tg * nheads + h) * HD + 2 * i;
    float u0 = p[0], u1 = p[1];
    p[0] = u0 * c - u1 * s;
    p[1] = u0 * s + u1 * c;
}

// ---------------- Flash attention (causal, GQA) ----------------------------
// grid: (SEQ/64, NH, BATCH), block: 64 threads; thread t owns query row t of
// its 64-row tile. K/V tiles staged in smem; scores broadcast-read.
__global__ void __launch_bounds__(64)
attn_kernel() {
    __shared__ float Ks[64][64];
    __shared__ float Vs[64][64];

    const int tid = threadIdx.x;
    const int qt  = blockIdx.x;
    const int h   = blockIdx.y;
    const int b   = blockIdx.z;
    const int kvh = h / GQA;
    const int qi  = qt * 64 + tid;

    float q[HD];
    const float* qp = g_q + ((size_t)(b * SEQ + qi) * NH + h) * HD;
#pragma unroll
    for (int d = 0; d < HD; d++) q[d] = qp[d] * 0.125f;  // 1/sqrt(64)

    float acc[HD];
#pragma unroll
    for (int d = 0; d < HD; d++) acc[d] = 0.f;
    float m = -CUDART_INF_F, l = 0.f;

    for (int kt = 0; kt <= qt; kt++) {
        __syncthreads();
        {
            const size_t kbase = ((size_t)(b * SEQ + kt * 64 + tid) * NKV + kvh) * HD;
            const float* kp = g_k + kbase;
            const float* vp = g_v + kbase;
#pragma unroll
            for (int d = 0; d < HD; d += 4) {
                *(float4*)&Ks[tid][d] = *(const float4*)&kp[d];
                *(float4*)&Vs[tid][d] = *(const float4*)&vp[d];
            }
        }
        __syncthreads();

        float s[64];
        float tmax = -CUDART_INF_F;
        const bool diag = (kt == qt);
        for (int j = 0; j < 64; j++) {
            float dot = 0.f;
#pragma unroll
            for (int d = 0; d < HD; d += 4) {
                float4 kv = *(const float4*)&Ks[j][d];
                dot = fmaf(q[d], kv.x, dot);
                dot = fmaf(q[d + 1], kv.y, dot);
                dot = fmaf(q[d + 2], kv.z, dot);
                dot = fmaf(q[d + 3], kv.w, dot);
            }
            if (diag && j > tid) dot = -CUDART_INF_F;
            s[j] = dot;
            tmax = fmaxf(tmax, dot);
        }

        float mnew = fmaxf(m, tmax);
        float corr = __expf(m - mnew);
        l *= corr;
#pragma unroll
        for (int d = 0; d < HD; d++) acc[d] *= corr;

        for (int j = 0; j < 64; j++) {
            float p = __expf(s[j] - mnew);
            l += p;
#pragma unroll
            for (int d = 0; d < HD; d += 4) {
                float4 vv = *(const float4*)&Vs[j][d];
                acc[d]     = fmaf(p, vv.x, acc[d]);
                acc[d + 1] = fmaf(p, vv.y, acc[d + 1]);
                acc[d + 2] = fmaf(p, vv.z, acc[d + 2]);
                acc[d + 3] = fmaf(p, vv.w, acc[d + 3]);
            }
        }
        m = mnew;
    }

    float inv = 1.f / l;
    float* op = g_attn + ((size_t)(b * SEQ + qi) * NH + h) * HD;
#pragma unroll
    for (int d = 0; d < HD; d++) op[d] = acc[d] * inv;
}

// ---------------- launcher --------------------------------------------------
extern "C" void kernel_launch(void* const* d_in, const int* in_sizes, int n_in,
                              void* d_out, int out_size) {
    const float* x    = (const float*)d_in[0];
    const float* fcos = (const float*)d_in[1];
    const float* fsin = (const float*)d_in[2];
    const float* wq   = (const float*)d_in[3];
    const float* wk   = (const float*)d_in[4];
    const float* wv   = (const float*)d_in[5];
    const float* wo   = (const float*)d_in[6];
    float* out = (float*)d_out;

    float *dq, *dk, *dv, *dattn;
    cudaGetSymbolAddress((void**)&dq,    g_q);
    cudaGetSymbolAddress((void**)&dk,    g_k);
    cudaGetSymbolAddress((void**)&dv,    g_v);
    cudaGetSymbolAddress((void**)&dattn, g_attn);

    dim3 blk(256);
    // Q = x @ wq  (8192 x 960)
    gemm_f32_kernel<<<dim3(NH * HD / TN, MTOK / TM), blk>>>(x, wq, dq, MTOK, NH * HD, DIM);
    // K = x @ wk  (8192 x 320)
    gemm_f32_kernel<<<dim3(NKV * HD / TN, MTOK / TM), blk>>>(x, wk, dk, MTOK, NKV * HD, DIM);
    // V = x @ wv  (8192 x 320)
    gemm_f32_kernel<<<dim3(NKV * HD / TN, MTOK / TM), blk>>>(x, wv, dv, MTOK, NKV * HD, DIM);

    // RoPE on q and k
    {
        int totq = MTOK * NH * (HD / 2);
        int totk = MTOK * NKV * (HD / 2);
        rope_kernel<<<(totq + 255) / 256, 256>>>(dq, fcos, fsin, NH, totq);
        rope_kernel<<<(totk + 255) / 256, 256>>>(dk, fcos, fsin, NKV, totk);
    }

    // Flash attention
    attn_kernel<<<dim3(SEQ / 64, NH, BATCH), 64>>>();

    // out = attn @ wo  (8192 x 960)
    gemm_f32_kernel<<<dim3(DIM / TN, MTOK / TM), blk>>>(dattn, wo, out, MTOK, DIM, DIM);
}

// round 4
// speedup vs baseline: 1.2184x; 1.2184x over previous
#include <cuda_runtime.h>
#include <cuda_bf16.h>
#include <math_constants.h>
#include <cstdint>

// Problem constants
#define BATCH 4
#define SEQ 2048
#define DIM 960
#define NH 15
#define NKV 5
#define HD 64
#define GQA 3
#define MTOK (BATCH*SEQ)   // 8192

// ---------------- scratch (device globals; no allocations) ----------------
__device__ float g_q[(size_t)MTOK * NH * HD];
__device__ float g_k[(size_t)MTOK * NKV * HD];
__device__ float g_v[(size_t)MTOK * NKV * HD];
__device__ float g_attn[(size_t)MTOK * NH * HD];

__device__ __nv_bfloat16 g_xhi[(size_t)MTOK * DIM];
__device__ __nv_bfloat16 g_xlo[(size_t)MTOK * DIM];
__device__ __nv_bfloat16 g_ahi[(size_t)MTOK * DIM];
__device__ __nv_bfloat16 g_alo[(size_t)MTOK * DIM];
__device__ __nv_bfloat16 g_wqt_hi[(size_t)960 * 960];
__device__ __nv_bfloat16 g_wqt_lo[(size_t)960 * 960];
__device__ __nv_bfloat16 g_wkt_hi[(size_t)320 * 960];
__device__ __nv_bfloat16 g_wkt_lo[(size_t)320 * 960];
__device__ __nv_bfloat16 g_wvt_hi[(size_t)320 * 960];
__device__ __nv_bfloat16 g_wvt_lo[(size_t)320 * 960];
__device__ __nv_bfloat16 g_wot_hi[(size_t)960 * 960];
__device__ __nv_bfloat16 g_wot_lo[(size_t)960 * 960];

// ---------------- small PTX helpers ------------------------------------------
__device__ __forceinline__ uint32_t smem_to_u32(const void* p) {
    uint32_t a;
    asm("{ .reg .u64 t; cvta.to.shared.u64 t, %1; cvt.u32.u64 %0, t; }" : "=r"(a) : "l"(p));
    return a;
}
__device__ __forceinline__ void cp_async16(uint32_t saddr, const void* gptr) {
    asm volatile("cp.async.cg.shared.global [%0], [%1], 16;" :: "r"(saddr), "l"(gptr));
}
#define CP_COMMIT() asm volatile("cp.async.commit_group;" ::: "memory")
#define CP_WAIT1()  asm volatile("cp.async.wait_group 1;" ::: "memory")

__device__ __forceinline__ void ldsm_x4(uint32_t* r, uint32_t addr) {
    asm volatile("ldmatrix.sync.aligned.m8n8.x4.shared.b16 {%0,%1,%2,%3}, [%4];"
                 : "=r"(r[0]), "=r"(r[1]), "=r"(r[2]), "=r"(r[3]) : "r"(addr));
}
__device__ __forceinline__ void mma_bf16(float* d, const uint32_t* a, const uint32_t* b) {
    asm volatile(
        "mma.sync.aligned.m16n8k16.row.col.f32.bf16.bf16.f32 "
        "{%0,%1,%2,%3}, {%4,%5,%6,%7}, {%8,%9}, {%0,%1,%2,%3};"
        : "+f"(d[0]), "+f"(d[1]), "+f"(d[2]), "+f"(d[3])
        : "r"(a[0]), "r"(a[1]), "r"(a[2]), "r"(a[3]), "r"(b[0]), "r"(b[1]));
}

// ---------------- bf16x3 GEMM on mma.sync -------------------------------------
// C[M,N] = A[M,K] @ B^T (B stored [N][K]), fp32 out, bf16x3 split inputs.
// Block tile 128x64, BK=32, 8 warps (4m x 2n), warp tile 32x32, 3-stage cp.async.
#define BM 128
#define BN 64
#define BK 32
#define NSTAGE 3
// smem per stage: Ah 128*80, Al 128*80, Bh 64*80, Bl 64*80
#define A_PITCH 80
#define SA_H 0
#define SA_L (128 * A_PITCH)
#define SB_H (2 * 128 * A_PITCH)
#define SB_L (SB_H + 64 * A_PITCH)
#define STAGE_BYTES (SB_L + 64 * A_PITCH)    // 30720
#define GEMM_SMEM (NSTAGE * STAGE_BYTES)     // 92160

__global__ void __launch_bounds__(256)
gemm_bf16x3_kernel(const __nv_bfloat16* __restrict__ Ahi,
                   const __nv_bfloat16* __restrict__ Alo,
                   const __nv_bfloat16* __restrict__ Bhi,
                   const __nv_bfloat16* __restrict__ Blo,
                   float* __restrict__ C, int M, int N, int K)
{
    extern __shared__ __align__(128) char smem[];
    const uint32_t sbase = smem_to_u32(smem);
    const int tid  = threadIdx.x;
    const int wid  = tid >> 5;
    const int lane = tid & 31;
    const int m0 = blockIdx.y * BM;
    const int n0 = blockIdx.x * BN;
    const int wm = wid >> 1;   // 0..3
    const int wn = wid & 1;    // 0..1

    const int nchunk = K / BK;

    // per-thread load coordinates
    const int arow = tid >> 1;            // 0..127 (2 threads per row)
    const int acol = (tid & 1) * 2;       // 16B chunk pairs
    const int brow = tid >> 2;            // 0..63
    const int bcol = tid & 3;             // 0..3

    auto load_stage = [&](int ci, int s) {
        const uint32_t st = sbase + s * STAGE_BYTES;
        const int k0 = ci * BK;
        {
            const size_t go = (size_t)(m0 + arow) * K + k0 + acol * 8;
            const uint32_t so = st + arow * A_PITCH + acol * 16;
            cp_async16(so,             Ahi + go);
            cp_async16(so + 16,        Ahi + go + 8);
            cp_async16(so + SA_L,      Alo + go);
            cp_async16(so + SA_L + 16, Alo + go + 8);
        }
        {
            const size_t go = (size_t)(n0 + brow) * K + k0 + bcol * 8;
            const uint32_t so = st + SB_H + brow * A_PITCH + bcol * 16;
            cp_async16(so,                Bhi + go);
            cp_async16(so + 64 * A_PITCH, Blo + go);
        }
    };

    float acc[2][4][4];
#pragma unroll
    for (int i = 0; i < 2; i++)
#pragma unroll
        for (int j = 0; j < 4; j++)
#pragma unroll
            for (int v = 0; v < 4; v++) acc[i][j][v] = 0.f;

    // prologue: 2 stages in flight
    load_stage(0, 0); CP_COMMIT();
    load_stage(1, 1); CP_COMMIT();

    // ldmatrix lane addressing
    const int a_r   = lane & 15;          // row within 16
    const int a_cb  = (lane >> 4) * 16;   // 0 or 16 bytes (k8 block)
    const int b_mat = lane >> 3;          // 0..3
    const int b_rin = lane & 7;
    const int b_nof = (b_mat >> 1) * 8 + b_rin;  // n within 16
    const int b_kb  = (b_mat & 1) * 16;          // 0 or 16 bytes

    for (int i = 0; i < nchunk; i++) {
        CP_WAIT1();
        __syncthreads();

        if (i + 2 < nchunk) load_stage(i + 2, (i + 2) % NSTAGE);
        CP_COMMIT();

        const uint32_t st = sbase + (i % NSTAGE) * STAGE_BYTES;

#pragma unroll
        for (int kk = 0; kk < 2; kk++) {      // two k16 sub-steps
            const int kbyte = kk * 32;
            uint32_t ah[2][4], al[2][4], bh[8], bl[8];
#pragma unroll
            for (int mt = 0; mt < 2; mt++) {
                uint32_t addr = st + (wm * 32 + mt * 16 + a_r) * A_PITCH + kbyte + a_cb;
                ldsm_x4(ah[mt], addr);
                ldsm_x4(al[mt], addr + SA_L);
            }
#pragma unroll
            for (int h = 0; h < 2; h++) {     // two n16 halves -> 4 n-tiles
                // B is [N][K] in smem == col-major kxn: NON-trans ldmatrix.
                uint32_t addr = st + SB_H + (wn * 32 + h * 16 + b_nof) * A_PITCH + kbyte + b_kb;
                ldsm_x4(&bh[h * 4], addr);
                ldsm_x4(&bl[h * 4], addr + 64 * A_PITCH);
            }
#pragma unroll
            for (int mt = 0; mt < 2; mt++)
#pragma unroll
                for (int nt = 0; nt < 4; nt++) {
                    mma_bf16(acc[mt][nt], ah[mt], &bh[nt * 2]);
                    mma_bf16(acc[mt][nt], ah[mt], &bl[nt * 2]);
                    mma_bf16(acc[mt][nt], al[mt], &bh[nt * 2]);
                }
        }
        __syncthreads();
    }

    // epilogue
#pragma unroll
    for (int mt = 0; mt < 2; mt++) {
#pragma unroll
        for (int nt = 0; nt < 4; nt++) {
            const int m = m0 + wm * 32 + mt * 16 + (lane >> 2);
            const int n = n0 + wn * 32 + nt * 8 + (lane & 3) * 2;
            *(float2*)&C[(size_t)m * N + n]       = make_float2(acc[mt][nt][0], acc[mt][nt][1]);
            *(float2*)&C[(size_t)(m + 8) * N + n] = make_float2(acc[mt][nt][2], acc[mt][nt][3]);
        }
    }
}

// ---------------- split / transpose helpers ---------------------------------
__global__ void convert_split_kernel(const float* __restrict__ src,
                                     __nv_bfloat16* __restrict__ hi,
                                     __nv_bfloat16* __restrict__ lo, int n) {
    int idx = blockIdx.x * blockDim.x + threadIdx.x;
    if (idx >= n) return;
    float a = src[idx];
    __nv_bfloat16 h = __float2bfloat16(a);
    hi[idx] = h;
    lo[idx] = __float2bfloat16(a - __bfloat162float(h));
}

// W[K][N] -> Wt_hi/lo[n*K + k]
__global__ void transpose_split_kernel(const float* __restrict__ W,
                                       __nv_bfloat16* __restrict__ hi,
                                       __nv_bfloat16* __restrict__ lo, int K, int N) {
    __shared__ float tile[32][33];
    int k0 = blockIdx.y * 32, n0 = blockIdx.x * 32;
    int tx = threadIdx.x, ty = threadIdx.y;  // (32, 8)
#pragma unroll
    for (int i = 0; i < 4; i++)
        tile[ty + i * 8][tx] = W[(size_t)(k0 + ty + i * 8) * N + n0 + tx];
    __syncthreads();
#pragma unroll
    for (int i = 0; i < 4; i++) {
        int n = n0 + ty + i * 8;
        float a = tile[tx][ty + i * 8];
        __nv_bfloat16 h = __float2bfloat16(a);
        hi[(size_t)n * K + k0 + tx] = h;
        lo[(size_t)n * K + k0 + tx] = __float2bfloat16(a - __bfloat162float(h));
    }
}

// ---------------- RoPE -------------------------------------------------------
__global__ void rope_kernel(float* __restrict__ buf,
                            const float* __restrict__ cosb,
                            const float* __restrict__ sinb,
                            int nheads, int total) {
    int idx = blockIdx.x * blockDim.x + threadIdx.x;
    if (idx >= total) return;
    int i = idx & 31;
    int rest = idx >> 5;
    int h = rest % nheads;
    int tg = rest / nheads;
    int t = tg & (SEQ - 1);
    float c = cosb[t * 32 + i];
    float s = sinb[t * 32 + i];
    float* p = buf + ((size_t)tg * nheads + h) * HD + 2 * i;
    float u0 = p[0], u1 = p[1];
    p[0] = u0 * c - u1 * s;
    p[1] = u0 * s + u1 * c;
}

// ---------------- Flash attention (causal, GQA), fp32 CUDA-core --------------
__global__ void __launch_bounds__(64)
attn_kernel() {
    __shared__ float Ks[64][64];
    __shared__ float Vs[64][64];

    const int tid = threadIdx.x;
    const int qt  = blockIdx.x;
    const int h   = blockIdx.y;
    const int b   = blockIdx.z;
    const int kvh = h / GQA;
    const int qi  = qt * 64 + tid;

    float q[HD];
    const float* qp = g_q + ((size_t)(b * SEQ + qi) * NH + h) * HD;
#pragma unroll
    for (int d = 0; d < HD; d++) q[d] = qp[d] * 0.125f;

    float acc[HD];
#pragma unroll
    for (int d = 0; d < HD; d++) acc[d] = 0.f;
    float m = -CUDART_INF_F, l = 0.f;

    for (int kt = 0; kt <= qt; kt++) {
        __syncthreads();
        {
            const size_t kbase = ((size_t)(b * SEQ + kt * 64 + tid) * NKV + kvh) * HD;
            const float* kp = g_k + kbase;
            const float* vp = g_v + kbase;
#pragma unroll
            for (int d = 0; d < HD; d += 4) {
                *(float4*)&Ks[tid][d] = *(const float4*)&kp[d];
                *(float4*)&Vs[tid][d] = *(const float4*)&vp[d];
            }
        }
        __syncthreads();

        float s[64];
        float tmax = -CUDART_INF_F;
        const bool diag = (kt == qt);
        for (int j = 0; j < 64; j++) {
            float dot = 0.f;
#pragma unroll
            for (int d = 0; d < HD; d += 4) {
                float4 kv = *(const float4*)&Ks[j][d];
                dot = fmaf(q[d], kv.x, dot);
                dot = fmaf(q[d + 1], kv.y, dot);
                dot = fmaf(q[d + 2], kv.z, dot);
                dot = fmaf(q[d + 3], kv.w, dot);
            }
            if (diag && j > tid) dot = -CUDART_INF_F;
            s[j] = dot;
            tmax = fmaxf(tmax, dot);
        }

        float mnew = fmaxf(m, tmax);
        float corr = __expf(m - mnew);
        l *= corr;
#pragma unroll
        for (int d = 0; d < HD; d++) acc[d] *= corr;

        for (int j = 0; j < 64; j++) {
            float p = __expf(s[j] - mnew);
            l += p;
#pragma unroll
            for (int d = 0; d < HD; d += 4) {
                float4 vv = *(const float4*)&Vs[j][d];
                acc[d]     = fmaf(p, vv.x, acc[d]);
                acc[d + 1] = fmaf(p, vv.y, acc[d + 1]);
                acc[d + 2] = fmaf(p, vv.z, acc[d + 2]);
                acc[d + 3] = fmaf(p, vv.w, acc[d + 3]);
            }
        }
        m = mnew;
    }

    float inv = 1.f / l;
    float* op = g_attn + ((size_t)(b * SEQ + qi) * NH + h) * HD;
#pragma unroll
    for (int d = 0; d < HD; d++) op[d] = acc[d] * inv;
}

// ---------------- launcher ----------------------------------------------------
extern "C" void kernel_launch(void* const* d_in, const int* in_sizes, int n_in,
                              void* d_out, int out_size) {
    const float* x    = (const float*)d_in[0];
    const float* fcos = (const float*)d_in[1];
    const float* fsin = (const float*)d_in[2];
    const float* wq   = (const float*)d_in[3];
    const float* wk   = (const float*)d_in[4];
    const float* wv   = (const float*)d_in[5];
    const float* wo   = (const float*)d_in[6];
    float* out = (float*)d_out;

    float *dq, *dk, *dv, *dattn;
    cudaGetSymbolAddress((void**)&dq,    g_q);
    cudaGetSymbolAddress((void**)&dk,    g_k);
    cudaGetSymbolAddress((void**)&dv,    g_v);
    cudaGetSymbolAddress((void**)&dattn, g_attn);
    __nv_bfloat16 *xhi, *xlo, *ahi, *alo, *wqh, *wql, *wkh, *wkl, *wvh, *wvl, *woh, *wol;
    cudaGetSymbolAddress((void**)&xhi, g_xhi);
    cudaGetSymbolAddress((void**)&xlo, g_xlo);
    cudaGetSymbolAddress((void**)&ahi, g_ahi);
    cudaGetSymbolAddress((void**)&alo, g_alo);
    cudaGetSymbolAddress((void**)&wqh, g_wqt_hi);
    cudaGetSymbolAddress((void**)&wql, g_wqt_lo);
    cudaGetSymbolAddress((void**)&wkh, g_wkt_hi);
    cudaGetSymbolAddress((void**)&wkl, g_wkt_lo);
    cudaGetSymbolAddress((void**)&wvh, g_wvt_hi);
    cudaGetSymbolAddress((void**)&wvl, g_wvt_lo);
    cudaGetSymbolAddress((void**)&woh, g_wot_hi);
    cudaGetSymbolAddress((void**)&wol, g_wot_lo);

    cudaFuncSetAttribute(gemm_bf16x3_kernel,
                         cudaFuncAttributeMaxDynamicSharedMemorySize, GEMM_SMEM);

    // splits
    {
        int n = MTOK * DIM;
        convert_split_kernel<<<(n + 255) / 256, 256>>>(x, xhi, xlo, n);
    }
    transpose_split_kernel<<<dim3(960 / 32, 960 / 32), dim3(32, 8)>>>(wq, wqh, wql, DIM, 960);
    transpose_split_kernel<<<dim3(320 / 32, 960 / 32), dim3(32, 8)>>>(wk, wkh, wkl, DIM, 320);
    transpose_split_kernel<<<dim3(320 / 32, 960 / 32), dim3(32, 8)>>>(wv, wvh, wvl, DIM, 320);
    transpose_split_kernel<<<dim3(960 / 32, 960 / 32), dim3(32, 8)>>>(wo, woh, wol, 960, 960);

    // projections (mma.sync bf16x3)
    gemm_bf16x3_kernel<<<dim3(960 / BN, MTOK / BM), 256, GEMM_SMEM>>>(xhi, xlo, wqh, wql, dq, MTOK, 960, DIM);
    gemm_bf16x3_kernel<<<dim3(320 / BN, MTOK / BM), 256, GEMM_SMEM>>>(xhi, xlo, wkh, wkl, dk, MTOK, 320, DIM);
    gemm_bf16x3_kernel<<<dim3(320 / BN, MTOK / BM), 256, GEMM_SMEM>>>(xhi, xlo, wvh, wvl, dv, MTOK, 320, DIM);

    // RoPE
    {
        int totq = MTOK * NH * (HD / 2);
        int totk = MTOK * NKV * (HD / 2);
        rope_kernel<<<(totq + 255) / 256, 256>>>(dq, fcos, fsin, NH, totq);
        rope_kernel<<<(totk + 255) / 256, 256>>>(dk, fcos, fsin, NKV, totk);
    }

    // attention
    attn_kernel<<<dim3(SEQ / 64, NH, BATCH), 64>>>();

    // output projection
    {
        int n = MTOK * 960;
        convert_split_kernel<<<(n + 255) / 256, 256>>>(dattn, ahi, alo, n);
    }
    gemm_bf16x3_kernel<<<dim3(960 / BN, MTOK / BM), 256, GEMM_SMEM>>>(ahi, alo, woh, wol, out, MTOK, 960, 960);
}

// round 7
// speedup vs baseline: 3.4738x; 2.8512x over previous
#include <cuda_runtime.h>
#include <cuda_bf16.h>
#include <math_constants.h>
#include <cstdint>

// Problem constants
#define BATCH 4
#define SEQ 2048
#define DIM 960
#define NH 15
#define NKV 5
#define HD 64
#define GQA 3
#define MTOK (BATCH*SEQ)   // 8192

// ---------------- scratch (device globals; no allocations) ----------------
__device__ float g_q[(size_t)MTOK * NH * HD];
__device__ float g_k[(size_t)MTOK * NKV * HD];
__device__ float g_v[(size_t)MTOK * NKV * HD];

__device__ __nv_bfloat16 g_xhi[(size_t)MTOK * DIM];
__device__ __nv_bfloat16 g_xlo[(size_t)MTOK * DIM];
__device__ __nv_bfloat16 g_ahi[(size_t)MTOK * DIM];   // attention out hi
__device__ __nv_bfloat16 g_alo[(size_t)MTOK * DIM];   // attention out lo
__device__ __nv_bfloat16 g_qhi[(size_t)MTOK * NH * HD];
__device__ __nv_bfloat16 g_qlo[(size_t)MTOK * NH * HD];
__device__ __nv_bfloat16 g_khi[(size_t)MTOK * NKV * HD];
__device__ __nv_bfloat16 g_klo[(size_t)MTOK * NKV * HD];
__device__ __nv_bfloat16 g_vhi[(size_t)MTOK * NKV * HD];
__device__ __nv_bfloat16 g_vlo[(size_t)MTOK * NKV * HD];
__device__ __nv_bfloat16 g_wqt_hi[(size_t)960 * 960];
__device__ __nv_bfloat16 g_wqt_lo[(size_t)960 * 960];
__device__ __nv_bfloat16 g_wkt_hi[(size_t)320 * 960];
__device__ __nv_bfloat16 g_wkt_lo[(size_t)320 * 960];
__device__ __nv_bfloat16 g_wvt_hi[(size_t)320 * 960];
__device__ __nv_bfloat16 g_wvt_lo[(size_t)320 * 960];
__device__ __nv_bfloat16 g_wot_hi[(size_t)960 * 960];
__device__ __nv_bfloat16 g_wot_lo[(size_t)960 * 960];

// ---------------- small PTX helpers ------------------------------------------
__device__ __forceinline__ uint32_t smem_to_u32(const void* p) {
    uint32_t a;
    asm("{ .reg .u64 t; cvta.to.shared.u64 t, %1; cvt.u32.u64 %0, t; }" : "=r"(a) : "l"(p));
    return a;
}
__device__ __forceinline__ void cp_async16(uint32_t saddr, const void* gptr) {
    asm volatile("cp.async.cg.shared.global [%0], [%1], 16;" :: "r"(saddr), "l"(gptr));
}
#define CP_COMMIT() asm volatile("cp.async.commit_group;" ::: "memory")
#define CP_WAIT1()  asm volatile("cp.async.wait_group 1;" ::: "memory")

__device__ __forceinline__ void ldsm_x4(uint32_t* r, uint32_t addr) {
    asm volatile("ldmatrix.sync.aligned.m8n8.x4.shared.b16 {%0,%1,%2,%3}, [%4];"
                 : "=r"(r[0]), "=r"(r[1]), "=r"(r[2]), "=r"(r[3]) : "r"(addr));
}
__device__ __forceinline__ void ldsm_x4_trans(uint32_t* r, uint32_t addr) {
    asm volatile("ldmatrix.sync.aligned.m8n8.x4.trans.shared.b16 {%0,%1,%2,%3}, [%4];"
                 : "=r"(r[0]), "=r"(r[1]), "=r"(r[2]), "=r"(r[3]) : "r"(addr));
}
__device__ __forceinline__ void mma_bf16(float* d, const uint32_t* a, const uint32_t* b) {
    asm volatile(
        "mma.sync.aligned.m16n8k16.row.col.f32.bf16.bf16.f32 "
        "{%0,%1,%2,%3}, {%4,%5,%6,%7}, {%8,%9}, {%0,%1,%2,%3};"
        : "+f"(d[0]), "+f"(d[1]), "+f"(d[2]), "+f"(d[3])
        : "r"(a[0]), "r"(a[1]), "r"(a[2]), "r"(a[3]), "r"(b[0]), "r"(b[1]));
}
__device__ __forceinline__ uint32_t pack2bf(__nv_bfloat16 a, __nv_bfloat16 b) {
    __nv_bfloat162 t = __halves2bfloat162(a, b);
    return *(uint32_t*)&t;
}

// ---------------- bf16x3 GEMM on mma.sync -------------------------------------
#define BM 128
#define BN 64
#define BK 32
#define NSTAGE 3
#define A_PITCH 80
#define SA_L (128 * A_PITCH)
#define SB_H (2 * 128 * A_PITCH)
#define STAGE_BYTES (SB_H + 2 * 64 * A_PITCH)    // 30720
#define GEMM_SMEM (NSTAGE * STAGE_BYTES)         // 92160

__global__ void __launch_bounds__(256)
gemm_bf16x3_kernel(const __nv_bfloat16* __restrict__ Ahi,
                   const __nv_bfloat16* __restrict__ Alo,
                   const __nv_bfloat16* __restrict__ Bhi,
                   const __nv_bfloat16* __restrict__ Blo,
                   float* __restrict__ C, int M, int N, int K)
{
    extern __shared__ __align__(128) char smem[];
    const uint32_t sbase = smem_to_u32(smem);
    const int tid  = threadIdx.x;
    const int wid  = tid >> 5;
    const int lane = tid & 31;
    const int m0 = blockIdx.y * BM;
    const int n0 = blockIdx.x * BN;
    const int wm = wid >> 1;
    const int wn = wid & 1;

    const int nchunk = K / BK;
    const int arow = tid >> 1;
    const int acol = (tid & 1) * 2;
    const int brow = tid >> 2;
    const int bcol = tid & 3;

    auto load_stage = [&](int ci, int s) {
        const uint32_t st = sbase + s * STAGE_BYTES;
        const int k0 = ci * BK;
        {
            const size_t go = (size_t)(m0 + arow) * K + k0 + acol * 8;
            const uint32_t so = st + arow * A_PITCH + acol * 16;
            cp_async16(so,             Ahi + go);
            cp_async16(so + 16,        Ahi + go + 8);
            cp_async16(so + SA_L,      Alo + go);
            cp_async16(so + SA_L + 16, Alo + go + 8);
        }
        {
            const size_t go = (size_t)(n0 + brow) * K + k0 + bcol * 8;
            const uint32_t so = st + SB_H + brow * A_PITCH + bcol * 16;
            cp_async16(so,                Bhi + go);
            cp_async16(so + 64 * A_PITCH, Blo + go);
        }
    };

    float acc[2][4][4];
#pragma unroll
    for (int i = 0; i < 2; i++)
#pragma unroll
        for (int j = 0; j < 4; j++)
#pragma unroll
            for (int v = 0; v < 4; v++) acc[i][j][v] = 0.f;

    load_stage(0, 0); CP_COMMIT();
    load_stage(1, 1); CP_COMMIT();

    const int a_r   = lane & 15;
    const int a_cb  = (lane >> 4) * 16;
    const int b_mat = lane >> 3;
    const int b_rin = lane & 7;
    const int b_nof = (b_mat >> 1) * 8 + b_rin;
    const int b_kb  = (b_mat & 1) * 16;

    for (int i = 0; i < nchunk; i++) {
        CP_WAIT1();
        __syncthreads();

        if (i + 2 < nchunk) load_stage(i + 2, (i + 2) % NSTAGE);
        CP_COMMIT();

        const uint32_t st = sbase + (i % NSTAGE) * STAGE_BYTES;

#pragma unroll
        for (int kk = 0; kk < 2; kk++) {
            const int kbyte = kk * 32;
            uint32_t ah[2][4], al[2][4], bh[8], bl[8];
#pragma unroll
            for (int mt = 0; mt < 2; mt++) {
                uint32_t addr = st + (wm * 32 + mt * 16 + a_r) * A_PITCH + kbyte + a_cb;
                ldsm_x4(ah[mt], addr);
                ldsm_x4(al[mt], addr + SA_L);
            }
#pragma unroll
            for (int h = 0; h < 2; h++) {
                uint32_t addr = st + SB_H + (wn * 32 + h * 16 + b_nof) * A_PITCH + kbyte + b_kb;
                ldsm_x4(&bh[h * 4], addr);
                ldsm_x4(&bl[h * 4], addr + 64 * A_PITCH);
            }
#pragma unroll
            for (int mt = 0; mt < 2; mt++)
#pragma unroll
                for (int nt = 0; nt < 4; nt++) {
                    mma_bf16(acc[mt][nt], ah[mt], &bh[nt * 2]);
                    mma_bf16(acc[mt][nt], ah[mt], &bl[nt * 2]);
                    mma_bf16(acc[mt][nt], al[mt], &bh[nt * 2]);
                }
        }
        __syncthreads();
    }

#pragma unroll
    for (int mt = 0; mt < 2; mt++) {
#pragma unroll
        for (int nt = 0; nt < 4; nt++) {
            const int m = m0 + wm * 32 + mt * 16 + (lane >> 2);
            const int n = n0 + wn * 32 + nt * 8 + (lane & 3) * 2;
            *(float2*)&C[(size_t)m * N + n]       = make_float2(acc[mt][nt][0], acc[mt][nt][1]);
            *(float2*)&C[(size_t)(m + 8) * N + n] = make_float2(acc[mt][nt][2], acc[mt][nt][3]);
        }
    }
}

// ---------------- split / transpose helpers ---------------------------------
__global__ void convert_split_kernel(const float* __restrict__ src,
                                     __nv_bfloat16* __restrict__ hi,
                                     __nv_bfloat16* __restrict__ lo, int n) {
    int idx = blockIdx.x * blockDim.x + threadIdx.x;
    if (idx >= n) return;
    float a = src[idx];
    __nv_bfloat16 h = __float2bfloat16(a);
    hi[idx] = h;
    lo[idx] = __float2bfloat16(a - __bfloat162float(h));
}

__global__ void transpose_split_kernel(const float* __restrict__ W,
                                       __nv_bfloat16* __restrict__ hi,
                                       __nv_bfloat16* __restrict__ lo, int K, int N) {
    __shared__ float tile[32][33];
    int k0 = blockIdx.y * 32, n0 = blockIdx.x * 32;
    int tx = threadIdx.x, ty = threadIdx.y;
#pragma unroll
    for (int i = 0; i < 4; i++)
        tile[ty + i * 8][tx] = W[(size_t)(k0 + ty + i * 8) * N + n0 + tx];
    __syncthreads();
#pragma unroll
    for (int i = 0; i < 4; i++) {
        int n = n0 + ty + i * 8;
        float a = tile[tx][ty + i * 8];
        __nv_bfloat16 h = __float2bfloat16(a);
        hi[(size_t)n * K + k0 + tx] = h;
        lo[(size_t)n * K + k0 + tx] = __float2bfloat16(a - __bfloat162float(h));
    }
}

// ---------------- RoPE + bf16 hi/lo split ------------------------------------
__global__ void rope_split_kernel(const float* __restrict__ src,
                                  __nv_bfloat16* __restrict__ hi,
                                  __nv_bfloat16* __restrict__ lo,
                                  const float* __restrict__ cosb,
                                  const float* __restrict__ sinb,
                                  int nheads, float scale, int total) {
    int idx = blockIdx.x * blockDim.x + threadIdx.x;
    if (idx >= total) return;
    int i = idx & 31;
    int rest = idx >> 5;
    int h = rest % nheads;
    int tg = rest / nheads;
    int t = tg & (SEQ - 1);
    float c = cosb[t * 32 + i];
    float s = sinb[t * 32 + i];
    size_t o = ((size_t)tg * nheads + h) * HD + 2 * i;
    const float* p = src + o;
    float u0 = p[0], u1 = p[1];
    float r0 = (u0 * c - u1 * s) * scale;
    float r1 = (u0 * s + u1 * c) * scale;
    __nv_bfloat16 h0 = __float2bfloat16(r0), h1 = __float2bfloat16(r1);
    __nv_bfloat16 l0 = __float2bfloat16(r0 - __bfloat162float(h0));
    __nv_bfloat16 l1 = __float2bfloat16(r1 - __bfloat162float(h1));
    *(uint32_t*)(hi + o) = pack2bf(h0, h1);
    *(uint32_t*)(lo + o) = pack2bf(l0, l1);
}

// ---------------- Flash attention on mma.sync (causal, GQA) -------------------
// block: 128 threads (4 warps), 64 q rows; warp w owns rows w*16..w*16+15.
#define AT_PITCH 144
#define AT_K_L 9216
#define AT_V_H 18432
#define AT_V_L 27648
#define AT_STAGE 36864
#define ATTN_SMEM (2 * AT_STAGE)   // 73728

__global__ void __launch_bounds__(128)
attn_mma_kernel(const __nv_bfloat16* __restrict__ Qhi, const __nv_bfloat16* __restrict__ Qlo,
                const __nv_bfloat16* __restrict__ Khi, const __nv_bfloat16* __restrict__ Klo,
                const __nv_bfloat16* __restrict__ Vhi, const __nv_bfloat16* __restrict__ Vlo,
                __nv_bfloat16* __restrict__ Ohi, __nv_bfloat16* __restrict__ Olo)
{
    extern __shared__ __align__(128) char smem[];
    const uint32_t sbase = smem_to_u32(smem);
    const int tid = threadIdx.x, wid = tid >> 5, lane = tid & 31;
    const int qt = blockIdx.x, h = blockIdx.y, b = blockIdx.z;
    const int kvh = h / GQA;

    // ---- stage Q through smem (stage 0 area), extract fragments
    {
        int r = tid >> 1, half = tid & 1;
        size_t gq = ((size_t)(b * SEQ + qt * 64 + r) * NH + h) * HD + half * 32;
        const uint4* ph = (const uint4*)(Qhi + gq);
        const uint4* pl = (const uint4*)(Qlo + gq);
        char* dsth = smem + r * AT_PITCH + half * 64;
        char* dstl = smem + AT_K_L + r * AT_PITCH + half * 64;
#pragma unroll
        for (int c = 0; c < 4; c++) { ((uint4*)dsth)[c] = ph[c]; ((uint4*)dstl)[c] = pl[c]; }
    }
    __syncthreads();
    uint32_t qh[4][4], ql[4][4];
    {
        const int a_r = lane & 15, a_cb = (lane >> 4) * 16;
#pragma unroll
        for (int kk = 0; kk < 4; kk++) {
            uint32_t addr = sbase + (wid * 16 + a_r) * AT_PITCH + kk * 32 + a_cb;
            ldsm_x4(qh[kk], addr);
            ldsm_x4(ql[kk], addr + AT_K_L);
        }
    }
    __syncthreads();

    auto load_kv = [&](int kt) {
        uint32_t st = sbase + (kt & 1) * AT_STAGE;
        int jr = tid >> 1, cs = (tid & 1) * 4;
        size_t g = ((size_t)(b * SEQ + kt * 64 + jr) * NKV + kvh) * HD + cs * 8;
        uint32_t so = st + jr * AT_PITCH + cs * 16;
#pragma unroll
        for (int c = 0; c < 4; c++) {
            cp_async16(so + c * 16,           Khi + g + c * 8);
            cp_async16(so + AT_K_L + c * 16,  Klo + g + c * 8);
            cp_async16(so + AT_V_H + c * 16,  Vhi + g + c * 8);
            cp_async16(so + AT_V_L + c * 16,  Vlo + g + c * 8);
        }
    };

    float O[8][4];
#pragma unroll
    for (int i = 0; i < 8; i++)
#pragma unroll
        for (int j = 0; j < 4; j++) O[i][j] = 0.f;
    float m0 = -CUDART_INF_F, m1 = -CUDART_INF_F;
    float l0 = 0.f, l1 = 0.f;

    load_kv(0); CP_COMMIT();
    if (qt >= 1) load_kv(1);
    CP_COMMIT();

    const int b_rin = lane & 7;
    const int b_mat = lane >> 3;
    const int b_nof = (b_mat >> 1) * 8 + b_rin;
    const int b_kb  = (b_mat & 1) * 16;
    const int v_r   = lane & 15;
    const int v_cb  = (lane >> 4) * 16;
    const int r0loc = wid * 16 + (lane >> 2);

    for (int kt = 0; kt <= qt; kt++) {
        CP_WAIT1();
        __syncthreads();
        const uint32_t st = sbase + (kt & 1) * AT_STAGE;

        // ---- S = Q K^T (3-pass bf16x2)
        float S[8][4];
#pragma unroll
        for (int i = 0; i < 8; i++)
#pragma unroll
            for (int j = 0; j < 4; j++) S[i][j] = 0.f;

#pragma unroll
        for (int kk = 0; kk < 4; kk++) {
            uint32_t kbh[16], kbl[16];
#pragma unroll
            for (int g2 = 0; g2 < 4; g2++) {
                uint32_t addr = st + (g2 * 16 + b_nof) * AT_PITCH + kk * 32 + b_kb;
                ldsm_x4(&kbh[g2 * 4], addr);
                ldsm_x4(&kbl[g2 * 4], addr + AT_K_L);
            }
#pragma unroll
            for (int nt = 0; nt < 8; nt++) {
                mma_bf16(S[nt], qh[kk], &kbh[nt * 2]);
                mma_bf16(S[nt], ql[kk], &kbh[nt * 2]);
                mma_bf16(S[nt], qh[kk], &kbl[nt * 2]);
            }
        }

        // ---- causal mask (diag tile only)
        if (kt == qt) {
#pragma unroll
            for (int nt = 0; nt < 8; nt++) {
                int col = nt * 8 + (lane & 3) * 2;
                if (col     > r0loc)     S[nt][0] = -CUDART_INF_F;
                if (col + 1 > r0loc)     S[nt][1] = -CUDART_INF_F;
                if (col     > r0loc + 8) S[nt][2] = -CUDART_INF_F;
                if (col + 1 > r0loc + 8) S[nt][3] = -CUDART_INF_F;
            }
        }

        // ---- online softmax
        float t0 = -CUDART_INF_F, t1 = -CUDART_INF_F;
#pragma unroll
        for (int nt = 0; nt < 8; nt++) {
            t0 = fmaxf(t0, fmaxf(S[nt][0], S[nt][1]));
            t1 = fmaxf(t1, fmaxf(S[nt][2], S[nt][3]));
        }
        t0 = fmaxf(t0, __shfl_xor_sync(0xffffffffu, t0, 1));
        t0 = fmaxf(t0, __shfl_xor_sync(0xffffffffu, t0, 2));
        t1 = fmaxf(t1, __shfl_xor_sync(0xffffffffu, t1, 1));
        t1 = fmaxf(t1, __shfl_xor_sync(0xffffffffu, t1, 2));
        float mn0 = fmaxf(m0, t0), mn1 = fmaxf(m1, t1);
        float c0 = __expf(m0 - mn0), c1 = __expf(m1 - mn1);
        m0 = mn0; m1 = mn1;

        // ---- P = exp(S - m), split hi/lo bf16 for high-precision PV
        uint32_t pkh[4][4], pkl[4][4];
        float la0 = 0.f, la1 = 0.f;
#pragma unroll
        for (int t = 0; t < 4; t++) {
            float p[8];
            p[0] = __expf(S[2*t][0] - mn0);   p[1] = __expf(S[2*t][1] - mn0);
            p[2] = __expf(S[2*t][2] - mn1);   p[3] = __expf(S[2*t][3] - mn1);
            p[4] = __expf(S[2*t+1][0] - mn0); p[5] = __expf(S[2*t+1][1] - mn0);
            p[6] = __expf(S[2*t+1][2] - mn1); p[7] = __expf(S[2*t+1][3] - mn1);
            la0 += p[0] + p[1] + p[4] + p[5];
            la1 += p[2] + p[3] + p[6] + p[7];
            __nv_bfloat16 hh[8], ll[8];
#pragma unroll
            for (int e = 0; e < 8; e++) {
                hh[e] = __float2bfloat16(p[e]);
                ll[e] = __float2bfloat16(p[e] - __bfloat162float(hh[e]));
            }
            pkh[t][0] = pack2bf(hh[0], hh[1]);  pkl[t][0] = pack2bf(ll[0], ll[1]);
            pkh[t][1] = pack2bf(hh[2], hh[3]);  pkl[t][1] = pack2bf(ll[2], ll[3]);
            pkh[t][2] = pack2bf(hh[4], hh[5]);  pkl[t][2] = pack2bf(ll[4], ll[5]);
            pkh[t][3] = pack2bf(hh[6], hh[7]);  pkl[t][3] = pack2bf(ll[6], ll[7]);
        }
        l0 = l0 * c0 + la0;
        l1 = l1 * c1 + la1;

#pragma unroll
        for (int dt = 0; dt < 8; dt++) {
            O[dt][0] *= c0; O[dt][1] *= c0;
            O[dt][2] *= c1; O[dt][3] *= c1;
        }

        // ---- O += P V (3-pass: Ph*Vh + Pl*Vh + Ph*Vl)
#pragma unroll
        for (int t = 0; t < 4; t++) {
            uint32_t vbh[16], vbl[16];
#pragma unroll
            for (int db = 0; db < 4; db++) {
                uint32_t addr = st + AT_V_H + (t * 16 + v_r) * AT_PITCH + db * 32 + v_cb;
                ldsm_x4_trans(&vbh[db * 4], addr);
                ldsm_x4_trans(&vbl[db * 4], addr + (AT_V_L - AT_V_H));
            }
#pragma unroll
            for (int dt = 0; dt < 8; dt++) {
                mma_bf16(O[dt], pkh[t], &vbh[dt * 2]);
                mma_bf16(O[dt], pkl[t], &vbh[dt * 2]);
                mma_bf16(O[dt], pkh[t], &vbl[dt * 2]);
            }
        }

        __syncthreads();
        if (kt + 2 <= qt) load_kv(kt + 2);
        CP_COMMIT();
    }

    // ---- finalize: normalize, split hi/lo, store
    l0 += __shfl_xor_sync(0xffffffffu, l0, 1);
    l0 += __shfl_xor_sync(0xffffffffu, l0, 2);
    l1 += __shfl_xor_sync(0xffffffffu, l1, 1);
    l1 += __shfl_xor_sync(0xffffffffu, l1, 2);
    float inv0 = 1.f / l0, inv1 = 1.f / l1;

    const int row0 = qt * 64 + r0loc;
#pragma unroll
    for (int dt = 0; dt < 8; dt++) {
        int d = dt * 8 + (lane & 3) * 2;
        size_t o0 = ((size_t)(b * SEQ + row0) * NH + h) * HD + d;
        size_t o1 = o0 + (size_t)8 * NH * HD;
        {
            float a = O[dt][0] * inv0, cc = O[dt][1] * inv0;
            __nv_bfloat16 ah = __float2bfloat16(a), ch = __float2bfloat16(cc);
            *(uint32_t*)(Ohi + o0) = pack2bf(ah, ch);
            *(uint32_t*)(Olo + o0) = pack2bf(__float2bfloat16(a - __bfloat162float(ah)),
                                             __float2bfloat16(cc - __bfloat162float(ch)));
        }
        {
            float a = O[dt][2] * inv1, cc = O[dt][3] * inv1;
            __nv_bfloat16 ah = __float2bfloat16(a), ch = __float2bfloat16(cc);
            *(uint32_t*)(Ohi + o1) = pack2bf(ah, ch);
            *(uint32_t*)(Olo + o1) = pack2bf(__float2bfloat16(a - __bfloat162float(ah)),
                                             __float2bfloat16(cc - __bfloat162float(ch)));
        }
    }
}

// ---------------- launcher ----------------------------------------------------
extern "C" void kernel_launch(void* const* d_in, const int* in_sizes, int n_in,
                              void* d_out, int out_size) {
    const float* x    = (const float*)d_in[0];
    const float* fcos = (const float*)d_in[1];
    const float* fsin = (const float*)d_in[2];
    const float* wq   = (const float*)d_in[3];
    const float* wk   = (const float*)d_in[4];
    const float* wv   = (const float*)d_in[5];
    const float* wo   = (const float*)d_in[6];
    float* out = (float*)d_out;

    float *dq, *dk, *dv;
    cudaGetSymbolAddress((void**)&dq, g_q);
    cudaGetSymbolAddress((void**)&dk, g_k);
    cudaGetSymbolAddress((void**)&dv, g_v);
    __nv_bfloat16 *xhi, *xlo, *ahi, *alo;
    __nv_bfloat16 *qhi, *qlo, *khi, *klo, *vhi, *vlo;
    __nv_bfloat16 *wqh, *wql, *wkh, *wkl, *wvh, *wvl, *woh, *wol;
    cudaGetSymbolAddress((void**)&xhi, g_xhi);
    cudaGetSymbolAddress((void**)&xlo, g_xlo);
    cudaGetSymbolAddress((void**)&ahi, g_ahi);
    cudaGetSymbolAddress((void**)&alo, g_alo);
    cudaGetSymbolAddress((void**)&qhi, g_qhi);
    cudaGetSymbolAddress((void**)&qlo, g_qlo);
    cudaGetSymbolAddress((void**)&khi, g_khi);
    cudaGetSymbolAddress((void**)&klo, g_klo);
    cudaGetSymbolAddress((void**)&vhi, g_vhi);
    cudaGetSymbolAddress((void**)&vlo, g_vlo);
    cudaGetSymbolAddress((void**)&wqh, g_wqt_hi);
    cudaGetSymbolAddress((void**)&wql, g_wqt_lo);
    cudaGetSymbolAddress((void**)&wkh, g_wkt_hi);
    cudaGetSymbolAddress((void**)&wkl, g_wkt_lo);
    cudaGetSymbolAddress((void**)&wvh, g_wvt_hi);
    cudaGetSymbolAddress((void**)&wvl, g_wvt_lo);
    cudaGetSymbolAddress((void**)&woh, g_wot_hi);
    cudaGetSymbolAddress((void**)&wol, g_wot_lo);

    cudaFuncSetAttribute(gemm_bf16x3_kernel,
                         cudaFuncAttributeMaxDynamicSharedMemorySize, GEMM_SMEM);
    cudaFuncSetAttribute(attn_mma_kernel,
                         cudaFuncAttributeMaxDynamicSharedMemorySize, ATTN_SMEM);

    // input split + weight transposes/splits
    {
        int n = MTOK * DIM;
        convert_split_kernel<<<(n + 255) / 256, 256>>>(x, xhi, xlo, n);
    }
    transpose_split_kernel<<<dim3(960 / 32, 960 / 32), dim3(32, 8)>>>(wq, wqh, wql, DIM, 960);
    transpose_split_kernel<<<dim3(320 / 32, 960 / 32), dim3(32, 8)>>>(wk, wkh, wkl, DIM, 320);
    transpose_split_kernel<<<dim3(320 / 32, 960 / 32), dim3(32, 8)>>>(wv, wvh, wvl, DIM, 320);
    transpose_split_kernel<<<dim3(960 / 32, 960 / 32), dim3(32, 8)>>>(wo, woh, wol, 960, 960);

    // projections (mma.sync bf16x3) -> fp32
    gemm_bf16x3_kernel<<<dim3(960 / BN, MTOK / BM), 256, GEMM_SMEM>>>(xhi, xlo, wqh, wql, dq, MTOK, 960, DIM);
    gemm_bf16x3_kernel<<<dim3(320 / BN, MTOK / BM), 256, GEMM_SMEM>>>(xhi, xlo, wkh, wkl, dk, MTOK, 320, DIM);
    gemm_bf16x3_kernel<<<dim3(320 / BN, MTOK / BM), 256, GEMM_SMEM>>>(xhi, xlo, wvh, wvl, dv, MTOK, 320, DIM);

    // RoPE + split (q pre-scaled by 1/sqrt(HD) = 0.125, exact in bf16)
    {
        int totq = MTOK * NH * (HD / 2);
        int totk = MTOK * NKV * (HD / 2);
        rope_split_kernel<<<(totq + 255) / 256, 256>>>(dq, qhi, qlo, fcos, fsin, NH, 0.125f, totq);
        rope_split_kernel<<<(totk + 255) / 256, 256>>>(dk, khi, klo, fcos, fsin, NKV, 1.0f, totk);
    }
    {
        int n = MTOK * NKV * HD;
        convert_split_kernel<<<(n + 255) / 256, 256>>>(dv, vhi, vlo, n);
    }

    // flash attention on tensor cores -> bf16 hi/lo attention output
    attn_mma_kernel<<<dim3(SEQ / 64, NH, BATCH), 128, ATTN_SMEM>>>(qhi, qlo, khi, klo, vhi, vlo, ahi, alo);

    // output projection
    gemm_bf16x3_kernel<<<dim3(960 / BN, MTOK / BM), 256, GEMM_SMEM>>>(ahi, alo, woh, wol, out, MTOK, 960, 960);
}